// round 2
// baseline (speedup 1.0000x reference)
#include <cuda_runtime.h>
#include <math.h>

// Problem-fixed sizes (inputs are a fixed dataset; runtime values are derived
// from in_sizes and fit these statics by construction).
#define NNODE 50000
#define EEDGE 200000
#define ESMAX (EEDGE + NNODE)
#define RNUM 65
#define HDIM 256
#define GNUM 1600
#define MDIM 64
#define MAXTILES 4096

// ---------------- device scratch (allocation-free rule: __device__ globals) ----
__device__ int   g_flag64[3];               // 1 if buffer is int64, else int32
__device__ int   g_esrc[EEDGE];
__device__ int   g_edst[EEDGE];
__device__ int   g_etype[EEDGE];
__device__ int   g_batch[NNODE];
__device__ float g_cnt[NNODE * RNUM];       // counts, then inverted in place
__device__ int   g_hist[RNUM];
__device__ int   g_cursor[RNUM];
__device__ int   g_ts[MAXTILES];
__device__ int   g_tc[MAXTILES];
__device__ int   g_tr[MAXTILES];
__device__ int   g_ntiles;
__device__ int   g_src[ESMAX];
__device__ int   g_dst[ESMAX];
__device__ float g_h1[(size_t)NNODE * HDIM];
__device__ float g_h2[(size_t)NNODE * HDIM];
__device__ float g_emb[GNUM * HDIM];

// ---------------- dtype detection (int32 vs int64 index buffers) --------------
// For little-endian int64 buffers holding values < 2^31, every odd 32-bit word
// is zero. Sample 256 odd words, bounded so we never read OOB under either
// interpretation (n is the element count; int32 view has >= n words).
__global__ void k_detect(const void* p0, int n0, const void* p1, int n1,
                         const void* p2, int n2)
{
    const unsigned int* p;
    int n;
    int b = blockIdx.x;
    if (b == 0)      { p = (const unsigned int*)p0; n = n0; }
    else if (b == 1) { p = (const unsigned int*)p1; n = n1; }
    else             { p = (const unsigned int*)p2; n = n2; }
    __shared__ int s_nz;
    if (threadIdx.x == 0) s_nz = 0;
    __syncthreads();
    int kmax = (n - 1) >> 1;
    if (kmax > 0) {
        int k = (int)(((long long)threadIdx.x * kmax) >> 8);
        if (p[2 * k + 1] != 0u) s_nz = 1;
    }
    __syncthreads();
    if (threadIdx.x == 0) g_flag64[b] = s_nz ? 0 : 1;
}

__global__ void k_convert_edges(const void* eidx, const void* ety, int E)
{
    int i = blockIdx.x * blockDim.x + threadIdx.x;
    if (i >= E) return;
    if (g_flag64[0]) {
        const long long* p = (const long long*)eidx;
        g_esrc[i] = (int)p[i];
        g_edst[i] = (int)p[E + i];
    } else {
        const int* p = (const int*)eidx;
        g_esrc[i] = p[i];
        g_edst[i] = p[E + i];
    }
    g_etype[i] = g_flag64[1] ? (int)((const long long*)ety)[i]
                             : ((const int*)ety)[i];
}

__global__ void k_convert_batch(const void* batch, int N)
{
    int i = blockIdx.x * blockDim.x + threadIdx.x;
    if (i >= N) return;
    g_batch[i] = g_flag64[2] ? (int)((const long long*)batch)[i]
                             : ((const int*)batch)[i];
}

// ---------------- counts / inverse counts ------------------------------------
__global__ void k_zero_cnt(int n)
{
    int i = blockIdx.x * blockDim.x + threadIdx.x;
    if (i < n) g_cnt[i] = 0.f;
}

__global__ void k_count(int E, int N)
{
    int i = blockIdx.x * blockDim.x + threadIdx.x;
    if (i < E) {
        atomicAdd(&g_cnt[g_edst[i] * RNUM + g_etype[i]], 1.f);
    } else if (i < E + N) {
        atomicAdd(&g_cnt[(i - E) * RNUM], 1.f);  // self loop, relation 0
    }
}

__global__ void k_invert(int n)
{
    int i = blockIdx.x * blockDim.x + threadIdx.x;
    if (i < n) g_cnt[i] = 1.f / fmaxf(g_cnt[i], 1.f);
}

// ---------------- counting sort by relation + tile build ----------------------
__global__ void k_zero_hist()
{
    if (threadIdx.x < RNUM) g_hist[threadIdx.x] = 0;
}

__global__ void k_hist(int E)
{
    int i = blockIdx.x * blockDim.x + threadIdx.x;
    if (i < E) atomicAdd(&g_hist[g_etype[i]], 1);
}

__global__ void k_scan_tiles(int N)
{
    if (blockIdx.x != 0 || threadIdx.x != 0) return;
    int off = 0, nt = 0;
    for (int r = 0; r < RNUM; r++) {
        int c = g_hist[r] + (r == 0 ? N : 0);  // relation 0 gains N self loops
        g_cursor[r] = off;
        for (int s = 0; s < c; s += 128) {
            g_ts[nt] = off + s;
            g_tc[nt] = (c - s < 128) ? (c - s) : 128;
            g_tr[nt] = r;
            nt++;
        }
        off += c;
    }
    g_ntiles = nt;
}

__global__ void k_scatter(int E, int N)
{
    int i = blockIdx.x * blockDim.x + threadIdx.x;
    if (i < E) {
        int r = g_etype[i];
        int p = atomicAdd(&g_cursor[r], 1);
        g_src[p] = g_esrc[i];
        g_dst[p] = g_edst[i];
    } else if (i < E + N) {
        int v = i - E;
        int p = atomicAdd(&g_cursor[0], 1);
        g_src[p] = v;
        g_dst[p] = v;
    }
}

// ---------------- dense root GEMM: out = bias + X @ Wr ------------------------
// 128x128 block tile, 8x8 microtile, K-tile 8. 256 threads.
__global__ __launch_bounds__(256) void k_dense(
    const float* __restrict__ X, const float* __restrict__ Wr,
    const float* __restrict__ bias, float* __restrict__ out, int N, int D)
{
    __shared__ float As[8][132];   // padded: conflict-reduced transposed stores
    __shared__ float Bs[8][128];

    int mbase = blockIdx.x * 128;
    int nbase = blockIdx.y * 128;
    int tid = threadIdx.x;
    int tm = tid & 15, tn = tid >> 4;
    int lm = tid >> 1, lkq = (tid & 1) * 4;    // A-load mapping
    int kk = tid >> 5, nn = (tid & 31) * 4;    // B-load mapping

    int rowA = mbase + lm;
    if (rowA >= N) rowA = N - 1;

    float acc[8][8];
#pragma unroll
    for (int i = 0; i < 8; i++)
#pragma unroll
        for (int j = 0; j < 8; j++) acc[i][j] = 0.f;

    for (int kb = 0; kb < D; kb += 8) {
        float4 a4 = *(const float4*)&X[(size_t)rowA * D + kb + lkq];
        As[lkq + 0][lm] = a4.x;
        As[lkq + 1][lm] = a4.y;
        As[lkq + 2][lm] = a4.z;
        As[lkq + 3][lm] = a4.w;
        float4 b4 = *(const float4*)&Wr[(size_t)(kb + kk) * HDIM + nbase + nn];
        *(float4*)&Bs[kk][nn] = b4;
        __syncthreads();
#pragma unroll
        for (int k = 0; k < 8; k++) {
            float a[8], b[8];
            *(float4*)&a[0] = *(const float4*)&As[k][tm * 8];
            *(float4*)&a[4] = *(const float4*)&As[k][tm * 8 + 4];
            *(float4*)&b[0] = *(const float4*)&Bs[k][tn * 8];
            *(float4*)&b[4] = *(const float4*)&Bs[k][tn * 8 + 4];
#pragma unroll
            for (int i = 0; i < 8; i++)
#pragma unroll
                for (int j = 0; j < 8; j++) acc[i][j] += a[i] * b[j];
        }
        __syncthreads();
    }

#pragma unroll
    for (int i = 0; i < 8; i++) {
        int row = mbase + tm * 8 + i;
        if (row < N) {
            float* op = &out[(size_t)row * HDIM + nbase + tn * 8];
            const float* bp = &bias[nbase + tn * 8];
#pragma unroll
            for (int j = 0; j < 8; j++) op[j] = bp[j] + acc[i][j];
        }
    }
}

// ---------------- relation-blocked edge GEMM + scatter -------------------------
// One block = (tile of <=128 edges of one relation) x (128 output cols).
// A row m = invcnt[dst_m, rel] * X[src_m, :]; B = W[rel]; atomicAdd into out[dst].
__global__ __launch_bounds__(256) void k_edge(
    const float* __restrict__ X, const float* __restrict__ Wall,
    float* __restrict__ out, int D)
{
    int t = blockIdx.x;
    if (t >= g_ntiles) return;
    int start = g_ts[t], cnt = g_tc[t], rel = g_tr[t];
    int nbase = blockIdx.y * 128;
    const float* Wr = Wall + (size_t)rel * D * HDIM;

    __shared__ float As[8][132];
    __shared__ float Bs[8][128];
    __shared__ int   s_srcv[128];
    __shared__ int   s_dst[128];
    __shared__ float s_inv[128];

    int tid = threadIdx.x;
    if (tid < 128) {
        int m = tid;
        if (m < cnt) {
            int e = start + m;
            int sv = g_src[e], dv = g_dst[e];
            s_srcv[m] = sv;
            s_dst[m]  = dv;
            s_inv[m]  = g_cnt[dv * RNUM + rel];   // inverted counts
        } else {
            s_srcv[m] = g_src[start];
            s_dst[m]  = -1;
            s_inv[m]  = 0.f;
        }
    }
    __syncthreads();

    int tm = tid & 15, tn = tid >> 4;
    int lm = tid >> 1, lkq = (tid & 1) * 4;
    int kk = tid >> 5, nn = (tid & 31) * 4;
    int rowA = s_srcv[lm];
    float sc = s_inv[lm];

    float acc[8][8];
#pragma unroll
    for (int i = 0; i < 8; i++)
#pragma unroll
        for (int j = 0; j < 8; j++) acc[i][j] = 0.f;

    for (int kb = 0; kb < D; kb += 8) {
        float4 a4 = *(const float4*)&X[(size_t)rowA * D + kb + lkq];
        As[lkq + 0][lm] = a4.x * sc;
        As[lkq + 1][lm] = a4.y * sc;
        As[lkq + 2][lm] = a4.z * sc;
        As[lkq + 3][lm] = a4.w * sc;
        float4 b4 = *(const float4*)&Wr[(size_t)(kb + kk) * HDIM + nbase + nn];
        *(float4*)&Bs[kk][nn] = b4;
        __syncthreads();
#pragma unroll
        for (int k = 0; k < 8; k++) {
            float a[8], b[8];
            *(float4*)&a[0] = *(const float4*)&As[k][tm * 8];
            *(float4*)&a[4] = *(const float4*)&As[k][tm * 8 + 4];
            *(float4*)&b[0] = *(const float4*)&Bs[k][tn * 8];
            *(float4*)&b[4] = *(const float4*)&Bs[k][tn * 8 + 4];
#pragma unroll
            for (int i = 0; i < 8; i++)
#pragma unroll
                for (int j = 0; j < 8; j++) acc[i][j] += a[i] * b[j];
        }
        __syncthreads();
    }

#pragma unroll
    for (int i = 0; i < 8; i++) {
        int m = tm * 8 + i;
        int dv = s_dst[m];
        if (dv >= 0) {
            float* op = &out[(size_t)dv * HDIM + nbase + tn * 8];
#pragma unroll
            for (int j = 0; j < 8; j++) atomicAdd(&op[j], acc[i][j]);
        }
    }
}

__global__ void k_relu(float* p, int n)
{
    int i = blockIdx.x * blockDim.x + threadIdx.x;
    if (i < n) p[i] = fmaxf(p[i], 0.f);
}

// ---------------- pooling (with fused ReLU on h2) ------------------------------
__global__ void k_zero_emb(int n)
{
    int i = blockIdx.x * blockDim.x + threadIdx.x;
    if (i < n) g_emb[i] = 0.f;
}

// emb[batch[i]] += sigmoid(relu(h_i) . ws + wsb) * relu(h_i)
__global__ void k_pool(const float* __restrict__ h, const float* __restrict__ wsw,
                       const float* __restrict__ wsb, int N)
{
    int gtid = blockIdx.x * blockDim.x + threadIdx.x;
    int node = gtid >> 5;
    int lane = gtid & 31;
    if (node >= N) return;
    const float* hr = h + (size_t)node * HDIM;
    float hv[8];
    float dot = 0.f;
#pragma unroll
    for (int q = 0; q < 8; q++) {
        hv[q] = fmaxf(hr[lane + 32 * q], 0.f);   // fused ReLU
        dot += hv[q] * wsw[lane + 32 * q];
    }
#pragma unroll
    for (int o = 16; o > 0; o >>= 1) dot += __shfl_xor_sync(0xFFFFFFFFu, dot, o);
    float w = 1.f / (1.f + expf(-(dot + wsb[0])));
    float* er = g_emb + (size_t)g_batch[node] * HDIM;
#pragma unroll
    for (int q = 0; q < 8; q++) atomicAdd(&er[lane + 32 * q], w * hv[q]);
}

// ---------------- fused MLP head: one block per graph -------------------------
__global__ void k_mlp(const float* __restrict__ m1w, const float* __restrict__ m1b,
                      const float* __restrict__ m2w, const float* __restrict__ m2b,
                      const float* __restrict__ m3w, const float* __restrict__ m3b,
                      const float* __restrict__ ow,  const float* __restrict__ ob,
                      float* __restrict__ out)
{
    __shared__ float se[HDIM];
    __shared__ float s1[MDIM];
    __shared__ float s2[MDIM];
    __shared__ float sr[MDIM];
    int g = blockIdx.x;
    int t = threadIdx.x;   // 64 threads
    for (int k = t; k < HDIM; k += MDIM) se[k] = g_emb[(size_t)g * HDIM + k];
    __syncthreads();
    float a = m1b[t];
    for (int k = 0; k < HDIM; k++) a += se[k] * m1w[k * MDIM + t];
    s1[t] = fmaxf(a, 0.f);
    __syncthreads();
    float b = m2b[t];
    for (int k = 0; k < MDIM; k++) b += s1[k] * m2w[k * MDIM + t];
    s2[t] = fmaxf(b, 0.f);
    __syncthreads();
    float c = m3b[t];
    for (int k = 0; k < MDIM; k++) c += s2[k] * m3w[k * MDIM + t];
    sr[t] = c * ow[t];
    __syncthreads();
    for (int o = 32; o > 0; o >>= 1) {
        if (t < o) sr[t] += sr[t + o];
        __syncthreads();
    }
    if (t == 0) out[g] = sr[0] + ob[0];
}

// ---------------- host side ----------------------------------------------------
extern "C" void kernel_launch(void* const* d_in, const int* in_sizes, int n_in,
                              void* d_out, int out_size)
{
    const float* x     = (const float*)d_in[0];
    const void*  eidx  = d_in[1];
    const void*  ety   = d_in[2];
    const void*  batch = d_in[3];
    const float* W1    = (const float*)d_in[4];
    const float* root1 = (const float*)d_in[5];
    const float* b1    = (const float*)d_in[6];
    const float* W2    = (const float*)d_in[7];
    const float* root2 = (const float*)d_in[8];
    const float* b2    = (const float*)d_in[9];
    const float* wsw   = (const float*)d_in[10];
    const float* wsb   = (const float*)d_in[11];
    const float* m1w   = (const float*)d_in[12];
    const float* m1b   = (const float*)d_in[13];
    const float* m2w   = (const float*)d_in[14];
    const float* m2b   = (const float*)d_in[15];
    const float* m3w   = (const float*)d_in[16];
    const float* m3b   = (const float*)d_in[17];
    const float* ow    = (const float*)d_in[18];
    const float* ob    = (const float*)d_in[19];
    float* out = (float*)d_out;

    int H = in_sizes[6];            // 256
    int F = in_sizes[5] / H;        // 128
    int N = in_sizes[0] / F;        // 50000
    int E = in_sizes[2];            // 200000
    int G = out_size;               // 1600

    float *p_h1 = nullptr, *p_h2 = nullptr;
    cudaGetSymbolAddress((void**)&p_h1, g_h1);
    cudaGetSymbolAddress((void**)&p_h2, g_h2);

    // --- index normalization + per-(node,relation) inverse counts ---
    k_detect<<<3, 256>>>(eidx, 2 * E, ety, E, batch, N);
    k_convert_edges<<<(E + 255) / 256, 256>>>(eidx, ety, E);
    k_convert_batch<<<(N + 255) / 256, 256>>>(batch, N);

    int ncnt = N * RNUM;
    k_zero_cnt<<<(ncnt + 255) / 256, 256>>>(ncnt);
    k_count<<<(E + N + 255) / 256, 256>>>(E, N);
    k_invert<<<(ncnt + 255) / 256, 256>>>(ncnt);

    // --- counting sort of (edges + self loops) by relation, tile build ---
    k_zero_hist<<<1, RNUM>>>();
    k_hist<<<(E + 255) / 256, 256>>>(E);
    k_scan_tiles<<<1, 1>>>(N);
    k_scatter<<<(E + N + 255) / 256, 256>>>(E, N);

    int ubTiles = (E + N + 127) / 128 + RNUM + 1;
    dim3 edgeGrid(ubTiles, H / 128);
    int nh = N * H;

    // --- layer 1: h1 = relu(b1 + X@root1 + edge aggregation with W1) ---
    k_dense<<<dim3((N + 127) / 128, H / 128), 256>>>(x, root1, b1, p_h1, N, F);
    k_edge<<<edgeGrid, 256>>>(x, W1, p_h1, F);
    k_relu<<<(nh + 255) / 256, 256>>>(p_h1, nh);

    // --- layer 2: h2 = b2 + h1@root2 + edge aggregation with W2 (ReLU fused in pool) ---
    k_dense<<<dim3((N + 127) / 128, H / 128), 256>>>(p_h1, root2, b2, p_h2, N, H);
    k_edge<<<edgeGrid, 256>>>(p_h1, W2, p_h2, H);

    // --- weighted-sum pooling (applies ReLU to h2 on the fly) ---
    k_zero_emb<<<(G * H + 255) / 256, 256>>>(G * H);
    k_pool<<<(N + 7) / 8, 256>>>(p_h2, wsw, wsb, N);

    // --- MLP head ---
    k_mlp<<<G, MDIM>>>(m1w, m1b, m2w, m2b, m3w, m3b, ow, ob, out);
}